// round 4
// baseline (speedup 1.0000x reference)
#include <cuda_runtime.h>
#include <math.h>

// Problem constants
#define BB 32
#define DD 512
#define KB 512            // codebook size
#define LLAT 1024         // latent positions per image (32*32)
#define NTOT (BB * LLAT)  // 32768 rows

// d_out layout: [recon (32*3*128*128)] [z_e (32*512*1024)] [emb (32*512*1024)]
#define RECON_ELEMS (32 * 3 * 128 * 128)
#define ZE_ELEMS (BB * DD * LLAT)

// Scratch (device globals: allocation-free)
__device__ float g_zq[(size_t)NTOT * DD];  // z_q in NCHW layout (b,d,p)
__device__ int g_idx[NTOT];
__device__ float g_w2[KB];
__device__ float g_wdt[DD * 48];  // decoder weights, flipped, [d][c*16+i*4+j]

// ---------------------------------------------------------------------------
// Prep: codebook column norms
__global__ void k_prep_w2(const float* __restrict__ cb) {
    int k = threadIdx.x;  // 512 threads
    float s = 0.f;
    for (int d = 0; d < DD; d++) {
        float v = cb[d * KB + k];
        s += v * v;
    }
    g_w2[k] = s;
}

// Prep: decoder weight transpose WITH spatial flip.
// jax conv_transpose (transpose_kernel=False, VALID, k=s=4):
//   out[b,c,4h+i,4w+j] = sum_d zq[b,d,h,w] * Wd[c,d,3-i,3-j] + bd[c]
__global__ void k_prep_wdt(const float* __restrict__ Wd) {
    int t = blockIdx.x * 256 + threadIdx.x;  // 24576 total
    int d = t / 48, m = t % 48;
    int c = m >> 4, ij = m & 15;
    int i = ij >> 2, j = ij & 3;
    g_wdt[t] = Wd[c * (DD * 16) + d * 16 + (3 - i) * 4 + (3 - j)];
}

// ---------------------------------------------------------------------------
// Encoder: z_e[b,d,p] = relu( sum_{c,i,j} x[b,c,4h+i,4w+j]*We[d,c,i,j] + be[d] )
// Block = 128 consecutive positions of one image; patch (48 floats) in regs,
// We streamed through smem in 128-channel chunks (broadcast reads).
__global__ void k_encoder(const float* __restrict__ x, const float* __restrict__ We,
                          const float* __restrict__ be, float* __restrict__ ze) {
    __shared__ float sW[128 * 48];  // 24 KB
    __shared__ float sB[DD];
    const int tid = threadIdx.x;  // 128
    const int blk = blockIdx.x;   // 256 blocks
    const int b = blk >> 3;
    const int p = ((blk & 7) << 7) + tid;  // 0..1023
    const int h = p >> 5, w = p & 31;

    for (int i = tid; i < DD; i += 128) sB[i] = be[i];

    float patch[48];
    const float* xb = x + (size_t)b * (3 * 128 * 128);
#pragma unroll
    for (int c = 0; c < 3; c++)
#pragma unroll
        for (int i = 0; i < 4; i++) {
            float4 v = *(const float4*)(xb + c * 16384 + (4 * h + i) * 128 + 4 * w);
            patch[c * 16 + i * 4 + 0] = v.x;
            patch[c * 16 + i * 4 + 1] = v.y;
            patch[c * 16 + i * 4 + 2] = v.z;
            patch[c * 16 + i * 4 + 3] = v.w;
        }

    float* zb = ze + (size_t)b * (DD * LLAT) + p;
    const float4* We4 = (const float4*)We;
    for (int dt = 0; dt < 4; dt++) {
        __syncthreads();
        float4* sW4 = (float4*)sW;
        for (int i = tid; i < 1536; i += 128) sW4[i] = We4[dt * 1536 + i];
        __syncthreads();
#pragma unroll 4
        for (int dl = 0; dl < 128; dl++) {
            const float* wr = sW + dl * 48;
            float a0 = 0.f, a1 = 0.f, a2 = 0.f, a3 = 0.f;
#pragma unroll
            for (int k = 0; k < 48; k += 4) {
                a0 += patch[k + 0] * wr[k + 0];
                a1 += patch[k + 1] * wr[k + 1];
                a2 += patch[k + 2] * wr[k + 2];
                a3 += patch[k + 3] * wr[k + 3];
            }
            int d = dt * 128 + dl;
            float s = (a0 + a1) + (a2 + a3) + sB[d];
            zb[(size_t)d * LLAT] = fmaxf(s, 0.f);
        }
    }
}

// ---------------------------------------------------------------------------
// Distance GEMM + fused argmin.
// cross[n,k] = sum_d z[n,d]*cb[d,k]; score = w2[k] - 2*cross. argmin over all K.
// Block: 64 rows; loops over 4 chunks of 128 k. BK=8, 256 threads, 4x8 microtile.
// z is read in NCHW layout (d-major rows, n contiguous) -> coalesced A tiles.
__global__ void k_argmin(const float* __restrict__ ze, const float* __restrict__ cb) {
    __shared__ float As[8][64];
    __shared__ float Bs[8][128];
    __shared__ float w2s[KB];
    const int tid = threadIdx.x;  // 256
    for (int i = tid; i < KB; i += 256) w2s[i] = g_w2[i];

    const int n0 = blockIdx.x * 64;  // 512 blocks
    const int b = n0 >> 10;
    const int p0 = n0 & 1023;
    const float* zb = ze + (size_t)b * (DD * LLAT) + p0;
    const int tx = tid & 15, ty = tid >> 4;

    float runv[4];
    int runi[4];
#pragma unroll
    for (int i = 0; i < 4; i++) { runv[i] = INFINITY; runi[i] = 0; }

    for (int kc = 0; kc < 4; kc++) {
        const int k0 = kc << 7;
        float acc[4][8];
#pragma unroll
        for (int i = 0; i < 4; i++)
#pragma unroll
            for (int j = 0; j < 8; j++) acc[i][j] = 0.f;

        for (int d0 = 0; d0 < DD; d0 += 8) {
            __syncthreads();
            if (tid < 128) {
                int dd = tid >> 4, m4 = (tid & 15) << 2;
                *(float4*)&As[dd][m4] = *(const float4*)(zb + (size_t)(d0 + dd) * LLAT + m4);
            }
            {
                int dd = tid >> 5, k4 = (tid & 31) << 2;
                *(float4*)&Bs[dd][k4] = *(const float4*)(cb + (d0 + dd) * KB + k0 + k4);
            }
            __syncthreads();
#pragma unroll
            for (int dd = 0; dd < 8; dd++) {
                float4 av = *(float4*)&As[dd][ty << 2];
                float4 b0 = *(float4*)&Bs[dd][tx << 3];
                float4 b1 = *(float4*)&Bs[dd][(tx << 3) + 4];
                float am[4] = {av.x, av.y, av.z, av.w};
                float bn[8] = {b0.x, b0.y, b0.z, b0.w, b1.x, b1.y, b1.z, b1.w};
#pragma unroll
                for (int i = 0; i < 4; i++)
#pragma unroll
                    for (int j = 0; j < 8; j++) acc[i][j] += am[i] * bn[j];
            }
        }
#pragma unroll
        for (int i = 0; i < 4; i++)
#pragma unroll
            for (int j = 0; j < 8; j++) {
                int k = k0 + (tx << 3) + j;
                float s = w2s[k] - 2.f * acc[i][j];
                if (s < runv[i] || (s == runv[i] && k < runi[i])) {
                    runv[i] = s;
                    runi[i] = k;
                }
            }
    }

    // Reduce across the 16 tx lanes sharing each row (lanes 0-15 / 16-31 of a warp)
#pragma unroll
    for (int i = 0; i < 4; i++) {
        float v = runv[i];
        int ix = runi[i];
#pragma unroll
        for (int off = 8; off >= 1; off >>= 1) {
            float ov = __shfl_xor_sync(0xffffffffu, v, off);
            int oi = __shfl_xor_sync(0xffffffffu, ix, off);
            if (ov < v || (ov == v && oi < ix)) { v = ov; ix = oi; }
        }
        if (tx == 0) g_idx[n0 + (ty << 2) + i] = ix;
    }
}

// ---------------------------------------------------------------------------
// Gather: emb = cb[:, idx]; z_q = z_e + (emb - z_e) (straight-through forward).
__global__ void k_gather(const float* __restrict__ cb, const float* __restrict__ ze,
                         float* __restrict__ emb) {
    size_t t = (size_t)blockIdx.x * 256 + threadIdx.x;  // 4194304 threads
    size_t e = t << 2;                                  // float4 index base
    int p = (int)(e & 1023);
    int d = (int)((e >> 10) & 511);
    int bi = (int)(e >> 19);
    int n0 = (bi << 10) + p;
    int4 iv = *(const int4*)(g_idx + n0);
    const float* cbd = cb + d * KB;
    float4 q;
    q.x = cbd[iv.x];
    q.y = cbd[iv.y];
    q.z = cbd[iv.z];
    q.w = cbd[iv.w];
    float4 z = *(const float4*)(ze + e);
    float4 zo;
    zo.x = z.x + (q.x - z.x);
    zo.y = z.y + (q.y - z.y);
    zo.z = z.z + (q.z - z.z);
    zo.w = z.w + (q.w - z.w);
    *(float4*)(emb + e) = q;
    *(float4*)(g_zq + e) = zo;
}

// ---------------------------------------------------------------------------
// Decoder: out[b,c,4h+i,4w+j] = sigmoid( sum_d zq[b,d,h,w]*wdt[d][c*16+i*4+j] + bd[c] )
// Block = one (b,h) row: 32 w positions x 48 outputs. 192 threads: (w, g), g owns 8 outs.
__global__ void k_decoder(const float* __restrict__ bd, float* __restrict__ out) {
    __shared__ float sz[64][32];
    __shared__ float sw[64][48];
    __shared__ float so[48][33];
    const int tid = threadIdx.x;  // 192
    const int blk = blockIdx.x;   // 1024 blocks
    const int b = blk >> 5, h = blk & 31;
    const float* zb = g_zq + (size_t)b * (DD * LLAT) + h * 32;
    const int w = tid & 31, g = tid >> 5;  // g in 0..5

    float acc[8];
#pragma unroll
    for (int q = 0; q < 8; q++) acc[q] = 0.f;

    for (int d0 = 0; d0 < DD; d0 += 64) {
        __syncthreads();
        for (int idx = tid; idx < 2048; idx += 192) {
            int dd = idx >> 5, ww = idx & 31;
            sz[dd][ww] = zb[(size_t)(d0 + dd) * LLAT + ww];
        }
        for (int idx = tid; idx < 3072; idx += 192)
            ((float*)sw)[idx] = g_wdt[d0 * 48 + idx];
        __syncthreads();
#pragma unroll 16
        for (int dd = 0; dd < 64; dd++) {
            float zv = sz[dd][w];
            float4 w0 = *(float4*)&sw[dd][g * 8];
            float4 w1 = *(float4*)&sw[dd][g * 8 + 4];
            acc[0] += zv * w0.x;
            acc[1] += zv * w0.y;
            acc[2] += zv * w0.z;
            acc[3] += zv * w0.w;
            acc[4] += zv * w1.x;
            acc[5] += zv * w1.y;
            acc[6] += zv * w1.z;
            acc[7] += zv * w1.w;
        }
    }

    __syncthreads();
#pragma unroll
    for (int q = 0; q < 8; q++) so[g * 8 + q][w] = acc[q];
    __syncthreads();

    float* ob = out + (size_t)b * (3 * 16384);
    for (int idx = tid; idx < 1536; idx += 192) {
        int r = idx >> 7;    // 0..11 : c = r>>2, i = r&3
        int col = idx & 127; // 4w + j
        int c = r >> 2, i = r & 3;
        int o = c * 16 + i * 4 + (col & 3);
        float v = so[o][col >> 2] + bd[c];
        ob[c * 16384 + (4 * h + i) * 128 + col] = 1.f / (1.f + expf(-v));
    }
}

// ---------------------------------------------------------------------------
extern "C" void kernel_launch(void* const* d_in, const int* in_sizes, int n_in,
                              void* d_out, int out_size) {
    const float* x = (const float*)d_in[0];
    const float* We = (const float*)d_in[1];
    const float* be = (const float*)d_in[2];
    const float* Wd = (const float*)d_in[3];
    const float* bd = (const float*)d_in[4];
    const float* cb = (const float*)d_in[5];

    float* out = (float*)d_out;
    float* recon = out;
    float* ze = out + RECON_ELEMS;
    float* emb = out + RECON_ELEMS + ZE_ELEMS;

    k_prep_w2<<<1, 512>>>(cb);
    k_prep_wdt<<<96, 256>>>(Wd);
    k_encoder<<<256, 128>>>(x, We, be, ze);
    k_argmin<<<512, 256>>>(ze, cb);
    k_gather<<<16384, 256>>>(cb, ze, emb);
    k_decoder<<<1024, 192>>>(bd, recon);
}